// round 16
// baseline (speedup 1.0000x reference)
#include <cuda_runtime.h>
#include <stdint.h>
#include <math.h>

#define BN 128
#define LN 2048
#define FN 128
#define HN 256
#define G3 768
#define NTICK 5
#define NC 128
#define NTH 256
#define NG 16      // groups
#define NDI 8      // CTAs per group (dim split)
#define SB 8       // batches per group

typedef unsigned long long u64;

// Scratch (module-scope device memory; no runtime allocation)
// h triple-buffer: [buf][g][kpair q(128)][s(8)][parity(2)] floats -> 8KB per group block
__device__ float d_Hbuf[3][NG * HN * SB];
__device__ float d_Hfinal[BN * HN];
__device__ int d_perm[BN];
__device__ int d_slen[BN];
__device__ unsigned d_gflag[NG * NDI * 32];   // per-CTA step flags, 128B apart

// ---------------- setup ----------------
__global__ __launch_bounds__(NTH) void setup_kernel(const int* __restrict__ lens) {
    __shared__ int sl[BN];
    int tid = threadIdx.x;
    if (tid < BN) sl[tid] = lens[tid];
    __syncthreads();
    if (tid < BN) {
        int ml = sl[tid];
        int r = 0;
        for (int i = 0; i < BN; i++) {
            int li = sl[i];
            if (li > ml || (li == ml && i < tid)) r++;
        }
        d_perm[r] = tid;
        d_slen[r] = ml;
    }
    for (int i = tid; i < NG * NDI * 32; i += NTH) d_gflag[i] = 0u;
    float* hb = &d_Hbuf[0][0];
    for (int i = tid; i < 3 * NG * HN * SB; i += NTH) hb[i] = 0.f;
}

// ---------------- packed f32x2 helpers ----------------
__device__ __forceinline__ void ff2(u64& acc, u64 a, u64 b) {
    asm("fma.rn.f32x2 %0, %1, %2, %0;" : "+l"(acc) : "l"(a), "l"(b));
}
__device__ __forceinline__ u64 add2(u64 a, u64 b) {
    u64 r; asm("add.rn.f32x2 %0, %1, %2;" : "=l"(r) : "l"(a), "l"(b)); return r;
}
__device__ __forceinline__ u64 pack_ab(float lo, float hi) {
    u64 r; asm("mov.b64 %0, {%1, %2};" : "=l"(r) : "f"(lo), "f"(hi)); return r;
}
__device__ __forceinline__ float2 unpk(u64 v) {
    float2 r; asm("mov.b64 {%0, %1}, %2;" : "=f"(r.x), "=f"(r.y) : "l"(v)); return r;
}

// ---------------- activations ----------------
__device__ __forceinline__ float fclamp15(float v) { return fminf(fmaxf(v, -15.f), 15.f); }
__device__ __forceinline__ float ftanh(float v) {
    float e = __expf(2.f * fclamp15(v));
    return __fdividef(e - 1.f, e + 1.f);
}
__device__ __forceinline__ float fsig(float v) {
    return __fdividef(1.f, 1.f + __expf(-fclamp15(v)));
}

// warp-cooperative poll: lane i watches flag slot i (NDI slots, 128B apart)
__device__ __forceinline__ void poll_flags(const unsigned* flags, unsigned tgt, int lane) {
    unsigned v = 0u;
    const unsigned* p = flags + lane * 32;
    for (;;) {
        if (lane < NDI)
            asm volatile("ld.acquire.gpu.global.u32 %0, [%1];" : "=r"(v) : "l"(p) : "memory");
        if (__all_sync(0xffffffffu, (lane >= NDI) | (v >= tgt))) break;
    }
}

// smem layout (floats)
// Rs stride = 196 floats/q (49 ull2): bank = (4q + 12*dgq) mod 32 -> conflict-free phases
#define SM_RS   0            // 128 q * 196 = 25088
#define SM_HS   25088        // 128 q * 20  = 2560
#define SM_XS   27648        // 2 * 64 q * 20 = 2560 (double buffered, 1280 each)
#define SM_PRJ  30208        // 512 floats projection scratch
#define SM_INT  30720        // sperm[128], slen[128]
#define SM_FLOATS 30976
#define SMEM_BYTES (SM_FLOATS * 4 + 64)

// ---------------- persistent lockstep LSTM + fused projections ----------------
// 128 CTAs = (di 0..8) x (g 0..16); 16 INDEPENDENT groups of 8 CTAs (one per g).
// CTA (di,g): dims [32di, 32di+32) x batches ranks [8g, 8g+8).
// Thread: ks = tid&15 (kpair-split), dgq = tid>>4 in [0,16) (dim pair).
// Body: x LDG + flag acquire pre-issue -> x-part FMAs (hides flag RTT) -> x STS
//   -> flag check (slow poll only if late) -> stage h (8KB) -> sync -> R-part
//   -> butterfly -> update -> publish -> sync -> release.
__global__ __launch_bounds__(NTH, 1) void lstm_kernel(
    const float* __restrict__ x, const float* __restrict__ W,
    const float* __restrict__ R, const float* __restrict__ b,
    const float* __restrict__ bt,
    const float* __restrict__ Wp, const float* __restrict__ bp,
    const float* __restrict__ Wo, const float* __restrict__ bo,
    float* __restrict__ out)
{
    extern __shared__ float sm[];
    float* Rs = sm + SM_RS;
    float* hs = sm + SM_HS;
    int* sperm = (int*)(sm + SM_INT);
    int* slen  = sperm + BN;

    const int tid = threadIdx.x;
    const int lane = tid & 31;
    const int bx  = blockIdx.x;
    const int di  = bx >> 4;        // 0..7
    const int g   = bx & 15;        // 0..15
    const int ks  = tid & 15;
    const int dgq = tid >> 4;       // 0..15
    const int down = ks >> 3;

    // ---- stage R slice: Rs[q*196 + dg*12 + d*6 + gt*2 + par] = R[2q+par][gt*HN + dim] ----
    for (int i = tid; i < 128 * 192; i += NTH) {
        int q = i / 192, r = i % 192;
        int dgl = r / 12, e = r % 12;
        int d = e / 6, gt = (e % 6) >> 1, par = e & 1;
        Rs[q * 196 + dgl * 12 + d * 6 + gt * 2 + par] =
            __ldg(&R[(2 * q + par) * G3 + gt * HN + (di << 5) + (dgl << 1) + d]);
    }
    if (tid < BN) { sperm[tid] = d_perm[tid]; slen[tid] = d_slen[tid]; }
    __syncthreads();

    // ---- x-part weights cached in registers, packed over k parity ----
    const int d0g = (di << 5) + (dgq << 1);
    u64 wx[4][6];
    #pragma unroll
    for (int i = 0; i < 4; i++) {
        int q = (i << 4) + ks;
        #pragma unroll
        for (int d = 0; d < 2; d++)
            #pragma unroll
            for (int gt = 0; gt < 3; gt++)
                wx[i][d * 3 + gt] = pack_ab(__ldg(&W[(2 * q) * G3 + gt * HN + d0g + d]),
                                            __ldg(&W[(2 * q + 1) * G3 + gt * HN + d0g + d]));
    }

    // ownership
    const int sown  = ks & 7;                 // local batch 0..7
    const int jglob = d0g + down;
    const int rank  = (g << 3) + sown;
    const int mylen = slen[rank];
    const int myb   = sperm[rank];
    const int myT   = mylen + NTICK;
    const int gMaxLen = slen[g << 3];         // sorted desc -> first of group is max
    const int gMaxT   = gMaxLen + NTICK;
    const float b0c = __ldg(&b[jglob]),  b1c = __ldg(&b[jglob + HN]),  b2c = __ldg(&b[jglob + 2 * HN]);
    const float t0c = __ldg(&bt[jglob]), t1c = __ldg(&bt[jglob + HN]), t2c = __ldg(&bt[jglob + 2 * HN]);
    unsigned* gflag = &d_gflag[g * NDI * 32];
    unsigned* myflag = gflag + di * 32;
    const unsigned* myPollAddr = gflag + lane * 32;   // lane < NDI watches CTA lane

    const ulonglong2* Rp = (const ulonglong2*)Rs;
    const ulonglong2* Hp = (const ulonglong2*)hs;

    // per-thread x staging index (256 float4s = 1 per thread)
    const int xsl = tid & 7;                  // batch slot
    const int xfq = tid >> 3;                 // float4 within row, 0..31
    const size_t xrow = (size_t)sperm[(g << 3) + xsl] * (LN * FN);
    const int xlen = slen[(g << 3) + xsl];

    // ---- prefetch x(0) into buffer 0 ----
    {
        float* xb = sm + SM_XS;
        float4 v = make_float4(0.f, 0.f, 0.f, 0.f);
        if (0 < xlen) v = __ldg((const float4*)(x + xrow) + xfq);
        ((float2*)xb)[(2 * xfq) * 10 + xsl]     = make_float2(v.x, v.y);
        ((float2*)xb)[(2 * xfq + 1) * 10 + xsl] = make_float2(v.z, v.w);
    }
    __syncthreads();

    float c = 0.f, h = 0.f;
    int cur = 0;   // t % 3

    for (int t = 0; t < gMaxT; t++) {
        const int nxt = (cur == 2) ? 0 : cur + 1;
        const int tp = t + 1;

#define FB6(bi, hv, W0, W1, W2, W3, W4, W5) \
    ff2(acc[bi][0], hv, W0); ff2(acc[bi][1], hv, W1); ff2(acc[bi][2], hv, W2); \
    ff2(acc[bi][3], hv, W3); ff2(acc[bi][4], hv, W4); ff2(acc[bi][5], hv, W5);

        // ---- A: issue x(t+1) LDG early (independent of everything) ----
        float4 xv = make_float4(0.f, 0.f, 0.f, 0.f);
        const bool doX = tp < gMaxLen;
        if (doX && tp < xlen)
            xv = __ldg((const float4*)(x + xrow + (size_t)tp * FN) + xfq);

        // ---- P1: pre-issue flag acquire loads (RTT hidden by B) ----
        unsigned vflag = 0u;
        if (t > 0 && lane < NDI)
            asm volatile("ld.acquire.gpu.global.u32 %0, [%1];"
                         : "=r"(vflag) : "l"(myPollAddr) : "memory");

        // ---- B: x-part FMAs into acc (x(t) already staged) ----
        u64 acc[8][6];
        #pragma unroll
        for (int bi = 0; bi < 8; bi++)
            #pragma unroll
            for (int e = 0; e < 6; e++) acc[bi][e] = 0ull;

        if (t < gMaxLen) {
            const ulonglong2* Xp = (const ulonglong2*)(sm + SM_XS + (t & 1) * 1280);
            #pragma unroll
            for (int i = 0; i < 4; i++) {
                const int q = (i << 4) + ks;
                const ulonglong2* xp = Xp + q * 5;
                ulonglong2 x0 = xp[0], x1 = xp[1], x2 = xp[2], x3 = xp[3];
                FB6(0, x0.x, wx[i][0], wx[i][1], wx[i][2], wx[i][3], wx[i][4], wx[i][5])
                FB6(1, x0.y, wx[i][0], wx[i][1], wx[i][2], wx[i][3], wx[i][4], wx[i][5])
                FB6(2, x1.x, wx[i][0], wx[i][1], wx[i][2], wx[i][3], wx[i][4], wx[i][5])
                FB6(3, x1.y, wx[i][0], wx[i][1], wx[i][2], wx[i][3], wx[i][4], wx[i][5])
                FB6(4, x2.x, wx[i][0], wx[i][1], wx[i][2], wx[i][3], wx[i][4], wx[i][5])
                FB6(5, x2.y, wx[i][0], wx[i][1], wx[i][2], wx[i][3], wx[i][4], wx[i][5])
                FB6(6, x3.x, wx[i][0], wx[i][1], wx[i][2], wx[i][3], wx[i][4], wx[i][5])
                FB6(7, x3.y, wx[i][0], wx[i][1], wx[i][2], wx[i][3], wx[i][4], wx[i][5])
            }
        }

        // ---- C: store x(t+1) into other x buffer (consumed next iter, after sync) ----
        if (doX) {
            float* xb = sm + SM_XS + (tp & 1) * 1280;
            ((float2*)xb)[(2 * xfq) * 10 + xsl]     = make_float2(xv.x, xv.y);
            ((float2*)xb)[(2 * xfq + 1) * 10 + xsl] = make_float2(xv.z, xv.w);
        }

        // ---- P2: check pre-issued flags; slow poll only if genuinely late ----
        if (t > 0) {
            if (!__all_sync(0xffffffffu, (lane >= NDI) | (vflag >= (unsigned)t)))
                poll_flags(gflag, (unsigned)t, lane);
        }

        // ---- E: stage h(t) tile 8KB from buffer cur (both LDGs before STS: MLP=2) ----
        {
            const float4* Hg4 = (const float4*)(&d_Hbuf[cur][g << 11]);
            float4* hs4w = (float4*)hs;
            int f0 = tid, f1 = tid + 256;
            float4 v0 = __ldcg(Hg4 + f0);
            float4 v1 = __ldcg(Hg4 + f1);
            hs4w[(f0 >> 2) * 5 + (f0 & 3)] = v0;
            hs4w[(f1 >> 2) * 5 + (f1 & 3)] = v1;
        }
        __syncthreads();

        {
            // ---- F: recurrent part: 8 kpair iters x 48 FFMA2 ----
            #pragma unroll
            for (int i = 0; i < 8; i++) {
                const int q = (i << 4) + ks;
                const ulonglong2* hp = Hp + q * 5;
                ulonglong2 h0 = hp[0], h1 = hp[1], h2 = hp[2], h3 = hp[3];
                const ulonglong2* wp = Rp + q * 49 + dgq * 3;
                ulonglong2 A = wp[0], Bv = wp[1], Cv = wp[2];
                FB6(0, h0.x, A.x, A.y, Bv.x, Bv.y, Cv.x, Cv.y)
                FB6(1, h0.y, A.x, A.y, Bv.x, Bv.y, Cv.x, Cv.y)
                FB6(2, h1.x, A.x, A.y, Bv.x, Bv.y, Cv.x, Cv.y)
                FB6(3, h1.y, A.x, A.y, Bv.x, Bv.y, Cv.x, Cv.y)
                FB6(4, h2.x, A.x, A.y, Bv.x, Bv.y, Cv.x, Cv.y)
                FB6(5, h2.y, A.x, A.y, Bv.x, Bv.y, Cv.x, Cv.y)
                FB6(6, h3.x, A.x, A.y, Bv.x, Bv.y, Cv.x, Cv.y)
                FB6(7, h3.y, A.x, A.y, Bv.x, Bv.y, Cv.x, Cv.y)
            }

            // ---- G: 4-round shedding butterfly over ks bits (packed u64) ----
            u64 r24[8][3];
            {
                const bool hi = down != 0;
                #pragma unroll
                for (int bi = 0; bi < 8; bi++)
                    #pragma unroll
                    for (int gt = 0; gt < 3; gt++) {
                        u64 send = hi ? acc[bi][gt] : acc[bi][3 + gt];
                        u64 recv = __shfl_xor_sync(0xffffffffu, send, 8);
                        u64 keep = hi ? acc[bi][3 + gt] : acc[bi][gt];
                        r24[bi][gt] = add2(keep, recv);
                    }
            }
            u64 r12[4][3];
            {
                const bool hb = (ks & 4) != 0;
                #pragma unroll
                for (int bi = 0; bi < 4; bi++)
                    #pragma unroll
                    for (int gt = 0; gt < 3; gt++) {
                        u64 send = hb ? r24[bi][gt] : r24[4 + bi][gt];
                        u64 recv = __shfl_xor_sync(0xffffffffu, send, 4);
                        u64 keep = hb ? r24[4 + bi][gt] : r24[bi][gt];
                        r12[bi][gt] = add2(keep, recv);
                    }
            }
            u64 r6[2][3];
            {
                const bool hb = (ks & 2) != 0;
                #pragma unroll
                for (int bi = 0; bi < 2; bi++)
                    #pragma unroll
                    for (int gt = 0; gt < 3; gt++) {
                        u64 send = hb ? r12[bi][gt] : r12[2 + bi][gt];
                        u64 recv = __shfl_xor_sync(0xffffffffu, send, 2);
                        u64 keep = hb ? r12[2 + bi][gt] : r12[bi][gt];
                        r6[bi][gt] = add2(keep, recv);
                    }
            }
            u64 r3[3];
            {
                const bool hb = (ks & 1) != 0;
                #pragma unroll
                for (int gt = 0; gt < 3; gt++) {
                    u64 send = hb ? r6[0][gt] : r6[1][gt];
                    u64 recv = __shfl_xor_sync(0xffffffffu, send, 1);
                    u64 keep = hb ? r6[1][gt] : r6[0][gt];
                    r3[gt] = add2(keep, recv);
                }
            }

            // ---- H: cell update; publish h(t+1) into buffer nxt ----
            if (t < myT) {
                float2 u0 = unpk(r3[0]), u1 = unpk(r3[1]), u2 = unpk(r3[2]);
                float p0 = u0.x + u0.y + b0c;
                float p1 = u1.x + u1.y + b1c;
                float p2 = u2.x + u2.y + b2c;
                if (t >= mylen) { p0 += t0c; p1 += t1c; p2 += t2c; }
                c = fmaf(ftanh(p0), fsig(p1), c);
                h = ftanh(c) * fsig(p2);
                __stcg(&d_Hbuf[nxt][(g << 11) + (jglob >> 1) * 16 + sown * 2 + (jglob & 1)], h);
                if (t == myT - 1) d_Hfinal[myb * HN + jglob] = h;
            }
        }
#undef FB6

        // ---- I: arrive: all CTA stores done -> release own flag ----
        __syncthreads();
        if (tid == 0) {
            asm volatile("st.release.gpu.global.u32 [%0], %1;"
                         :: "l"(myflag), "r"((unsigned)tp) : "memory");
        }
        cur = nxt;
    }

    // ---- wait for whole group, then fused projections ----
    poll_flags(gflag, (unsigned)gMaxT, lane);
    __syncthreads();

    const int ob = sperm[(g << 3) + di];
    float* hrow = sm + SM_PRJ;
    float* tmp  = hrow + 256;
    hrow[tid] = __ldcg(&d_Hfinal[ob * HN + tid]);
    __syncthreads();
    {
        const float4* wrow = (const float4*)(Wp + tid * HN);
        const float4* hv = (const float4*)hrow;
        float acc = __ldg(&bp[tid]);
        #pragma unroll 8
        for (int q = 0; q < HN / 4; q++) {
            float4 w = __ldg(&wrow[q]);
            float4 hh = hv[q];
            acc = fmaf(w.x, hh.x, acc); acc = fmaf(w.y, hh.y, acc);
            acc = fmaf(w.z, hh.z, acc); acc = fmaf(w.w, hh.w, acc);
        }
        tmp[tid] = acc;
    }
    __syncthreads();
    if (tid < 128) {
        const float4* wrow = (const float4*)(Wo + tid * HN);
        const float4* tv = (const float4*)tmp;
        float acc = __ldg(&bo[tid]);
        #pragma unroll 8
        for (int q = 0; q < HN / 4; q++) {
            float4 w = __ldg(&wrow[q]);
            float4 tt = tv[q];
            acc = fmaf(w.x, tt.x, acc); acc = fmaf(w.y, tt.y, acc);
            acc = fmaf(w.z, tt.z, acc); acc = fmaf(w.w, tt.w, acc);
        }
        out[ob * 128 + tid] = acc;
    }
}

extern "C" void kernel_launch(void* const* d_in, const int* in_sizes, int n_in,
                              void* d_out, int out_size) {
    const float* x    = (const float*)d_in[0];
    const int*   lens = (const int*)d_in[1];
    const float* W    = (const float*)d_in[2];
    const float* R    = (const float*)d_in[3];
    const float* b    = (const float*)d_in[4];
    const float* bt   = (const float*)d_in[5];
    const float* Wp   = (const float*)d_in[6];
    const float* bp   = (const float*)d_in[7];
    const float* Wo   = (const float*)d_in[8];
    const float* bo   = (const float*)d_in[9];
    float* out = (float*)d_out;

    cudaFuncSetAttribute(lstm_kernel, cudaFuncAttributeMaxDynamicSharedMemorySize, SMEM_BYTES);

    setup_kernel<<<1, NTH>>>(lens);
    lstm_kernel<<<NC, NTH, SMEM_BYTES>>>(x, W, R, b, bt, Wp, bp, Wo, bo, out);
}

// round 17
// speedup vs baseline: 1.1379x; 1.1379x over previous
#include <cuda_runtime.h>
#include <stdint.h>
#include <math.h>

#define BN 128
#define LN 2048
#define FN 128
#define HN 256
#define G3 768
#define NTICK 5
#define NC 128
#define NTH 256
#define NG 16      // groups
#define NDI 8      // CTAs per group (dim split)
#define SB 8       // batches per group

typedef unsigned long long u64;

// Scratch (module-scope device memory; no runtime allocation)
// h triple-buffer: [buf][g][kpair q(128)][s(8)][parity(2)] floats -> 8KB per group block
__device__ float d_Hbuf[3][NG * HN * SB];
__device__ float d_Hfinal[BN * HN];
__device__ int d_perm[BN];
__device__ int d_slen[BN];
__device__ unsigned d_gflag[NG * NDI * 32];   // per-CTA step flags, 128B apart

// ---------------- setup ----------------
__global__ __launch_bounds__(NTH) void setup_kernel(const int* __restrict__ lens) {
    __shared__ int sl[BN];
    int tid = threadIdx.x;
    if (tid < BN) sl[tid] = lens[tid];
    __syncthreads();
    if (tid < BN) {
        int ml = sl[tid];
        int r = 0;
        for (int i = 0; i < BN; i++) {
            int li = sl[i];
            if (li > ml || (li == ml && i < tid)) r++;
        }
        d_perm[r] = tid;
        d_slen[r] = ml;
    }
    for (int i = tid; i < NG * NDI * 32; i += NTH) d_gflag[i] = 0u;
    float* hb = &d_Hbuf[0][0];
    for (int i = tid; i < 3 * NG * HN * SB; i += NTH) hb[i] = 0.f;
}

// ---------------- packed f32x2 helpers ----------------
__device__ __forceinline__ void ff2(u64& acc, u64 a, u64 b) {
    asm("fma.rn.f32x2 %0, %1, %2, %0;" : "+l"(acc) : "l"(a), "l"(b));
}
__device__ __forceinline__ u64 add2(u64 a, u64 b) {
    u64 r; asm("add.rn.f32x2 %0, %1, %2;" : "=l"(r) : "l"(a), "l"(b)); return r;
}
__device__ __forceinline__ u64 pack_ab(float lo, float hi) {
    u64 r; asm("mov.b64 %0, {%1, %2};" : "=l"(r) : "f"(lo), "f"(hi)); return r;
}
__device__ __forceinline__ float2 unpk(u64 v) {
    float2 r; asm("mov.b64 {%0, %1}, %2;" : "=f"(r.x), "=f"(r.y) : "l"(v)); return r;
}

// ---------------- activations ----------------
__device__ __forceinline__ float fclamp15(float v) { return fminf(fmaxf(v, -15.f), 15.f); }
__device__ __forceinline__ float ftanh(float v) {
    float e = __expf(2.f * fclamp15(v));
    return __fdividef(e - 1.f, e + 1.f);
}
__device__ __forceinline__ float fsig(float v) {
    return __fdividef(1.f, 1.f + __expf(-fclamp15(v)));
}

// warp-cooperative poll: lane i watches flag slot i (NDI slots, 128B apart)
__device__ __forceinline__ void poll_flags(const unsigned* flags, unsigned tgt, int lane) {
    unsigned v = 0u;
    const unsigned* p = flags + lane * 32;
    for (;;) {
        if (lane < NDI)
            asm volatile("ld.acquire.gpu.global.u32 %0, [%1];" : "=r"(v) : "l"(p) : "memory");
        if (__all_sync(0xffffffffu, (lane >= NDI) | (v >= tgt))) break;
    }
}

// smem layout (floats)
// Rs stride = 196 floats/q (49 ull2): bank = (4q + 12*dgq) mod 32 -> conflict-free phases
#define SM_RS   0            // 128 q * 196 = 25088
#define SM_HS   25088        // 128 q * 20  = 2560
#define SM_XS   27648        // 2 * 64 q * 20 = 2560 (double buffered, 1280 each)
#define SM_PRJ  30208        // 512 floats projection scratch
#define SM_INT  30720        // sperm[128], slen[128]
#define SM_FLOATS 30976
#define SMEM_BYTES (SM_FLOATS * 4 + 64)

// ---------------- persistent lockstep LSTM + fused projections ----------------
// 128 CTAs = (di 0..8) x (g 0..16); 16 INDEPENDENT groups of 8 CTAs (one per g).
// CTA (di,g): dims [32di, 32di+32) x batches ranks [8g, 8g+8).
// Thread: ks = tid&15 (kpair-split), dgq = tid>>4 in [0,16) (dim pair).
// Body: x LDG issue -> x-part FMAs -> x STS -> poll flags(t) -> stage h (8KB) -> sync
//       -> R-part -> butterfly -> update -> store h(t+1) -> sync -> st.release flag.
__global__ __launch_bounds__(NTH, 1) void lstm_kernel(
    const float* __restrict__ x, const float* __restrict__ W,
    const float* __restrict__ R, const float* __restrict__ b,
    const float* __restrict__ bt,
    const float* __restrict__ Wp, const float* __restrict__ bp,
    const float* __restrict__ Wo, const float* __restrict__ bo,
    float* __restrict__ out)
{
    extern __shared__ float sm[];
    float* Rs = sm + SM_RS;
    float* hs = sm + SM_HS;
    int* sperm = (int*)(sm + SM_INT);
    int* slen  = sperm + BN;

    const int tid = threadIdx.x;
    const int lane = tid & 31;
    const int bx  = blockIdx.x;
    const int di  = bx >> 4;        // 0..7
    const int g   = bx & 15;        // 0..15
    const int ks  = tid & 15;
    const int dgq = tid >> 4;       // 0..15
    const int down = ks >> 3;

    // ---- stage R slice: Rs[q*196 + dg*12 + d*6 + gt*2 + par] = R[2q+par][gt*HN + dim] ----
    for (int i = tid; i < 128 * 192; i += NTH) {
        int q = i / 192, r = i % 192;
        int dgl = r / 12, e = r % 12;
        int d = e / 6, gt = (e % 6) >> 1, par = e & 1;
        Rs[q * 196 + dgl * 12 + d * 6 + gt * 2 + par] =
            __ldg(&R[(2 * q + par) * G3 + gt * HN + (di << 5) + (dgl << 1) + d]);
    }
    if (tid < BN) { sperm[tid] = d_perm[tid]; slen[tid] = d_slen[tid]; }
    __syncthreads();

    // ---- x-part weights cached in registers, packed over k parity ----
    const int d0g = (di << 5) + (dgq << 1);
    u64 wx[4][6];
    #pragma unroll
    for (int i = 0; i < 4; i++) {
        int q = (i << 4) + ks;
        #pragma unroll
        for (int d = 0; d < 2; d++)
            #pragma unroll
            for (int gt = 0; gt < 3; gt++)
                wx[i][d * 3 + gt] = pack_ab(__ldg(&W[(2 * q) * G3 + gt * HN + d0g + d]),
                                            __ldg(&W[(2 * q + 1) * G3 + gt * HN + d0g + d]));
    }

    // ownership
    const int sown  = ks & 7;                 // local batch 0..7
    const int jglob = d0g + down;
    const int rank  = (g << 3) + sown;
    const int mylen = slen[rank];
    const int myb   = sperm[rank];
    const int myT   = mylen + NTICK;
    const int gMaxLen = slen[g << 3];         // sorted desc -> first of group is max
    const int gMaxT   = gMaxLen + NTICK;
    const float b0c = __ldg(&b[jglob]),  b1c = __ldg(&b[jglob + HN]),  b2c = __ldg(&b[jglob + 2 * HN]);
    const float t0c = __ldg(&bt[jglob]), t1c = __ldg(&bt[jglob + HN]), t2c = __ldg(&bt[jglob + 2 * HN]);
    unsigned* gflag = &d_gflag[g * NDI * 32];
    unsigned* myflag = gflag + di * 32;

    const ulonglong2* Rp = (const ulonglong2*)Rs;
    const ulonglong2* Hp = (const ulonglong2*)hs;

    // per-thread x staging index (256 float4s = 1 per thread)
    const int xsl = tid & 7;                  // batch slot
    const int xfq = tid >> 3;                 // float4 within row, 0..31
    const size_t xrow = (size_t)sperm[(g << 3) + xsl] * (LN * FN);
    const int xlen = slen[(g << 3) + xsl];

    // ---- prefetch x(0) into buffer 0 ----
    {
        float* xb = sm + SM_XS;
        float4 v = make_float4(0.f, 0.f, 0.f, 0.f);
        if (0 < xlen) v = __ldg((const float4*)(x + xrow) + xfq);
        ((float2*)xb)[(2 * xfq) * 10 + xsl]     = make_float2(v.x, v.y);
        ((float2*)xb)[(2 * xfq + 1) * 10 + xsl] = make_float2(v.z, v.w);
    }
    __syncthreads();

    float c = 0.f, h = 0.f;
    int cur = 0;   // t % 3

    for (int t = 0; t < gMaxT; t++) {
        const int nxt = (cur == 2) ? 0 : cur + 1;
        const int tp = t + 1;

#define FB6(bi, hv, W0, W1, W2, W3, W4, W5) \
    ff2(acc[bi][0], hv, W0); ff2(acc[bi][1], hv, W1); ff2(acc[bi][2], hv, W2); \
    ff2(acc[bi][3], hv, W3); ff2(acc[bi][4], hv, W4); ff2(acc[bi][5], hv, W5);

        // ---- A: issue x(t+1) LDG early (independent of everything) ----
        float4 xv = make_float4(0.f, 0.f, 0.f, 0.f);
        const bool doX = tp < gMaxLen;
        if (doX && tp < xlen)
            xv = __ldg((const float4*)(x + xrow + (size_t)tp * FN) + xfq);

        // ---- B: x-part FMAs into acc BEFORE the poll (x(t) already staged) ----
        u64 acc[8][6];
        #pragma unroll
        for (int bi = 0; bi < 8; bi++)
            #pragma unroll
            for (int e = 0; e < 6; e++) acc[bi][e] = 0ull;

        if (t < gMaxLen) {
            const ulonglong2* Xp = (const ulonglong2*)(sm + SM_XS + (t & 1) * 1280);
            #pragma unroll
            for (int i = 0; i < 4; i++) {
                const int q = (i << 4) + ks;
                const ulonglong2* xp = Xp + q * 5;
                ulonglong2 x0 = xp[0], x1 = xp[1], x2 = xp[2], x3 = xp[3];
                FB6(0, x0.x, wx[i][0], wx[i][1], wx[i][2], wx[i][3], wx[i][4], wx[i][5])
                FB6(1, x0.y, wx[i][0], wx[i][1], wx[i][2], wx[i][3], wx[i][4], wx[i][5])
                FB6(2, x1.x, wx[i][0], wx[i][1], wx[i][2], wx[i][3], wx[i][4], wx[i][5])
                FB6(3, x1.y, wx[i][0], wx[i][1], wx[i][2], wx[i][3], wx[i][4], wx[i][5])
                FB6(4, x2.x, wx[i][0], wx[i][1], wx[i][2], wx[i][3], wx[i][4], wx[i][5])
                FB6(5, x2.y, wx[i][0], wx[i][1], wx[i][2], wx[i][3], wx[i][4], wx[i][5])
                FB6(6, x3.x, wx[i][0], wx[i][1], wx[i][2], wx[i][3], wx[i][4], wx[i][5])
                FB6(7, x3.y, wx[i][0], wx[i][1], wx[i][2], wx[i][3], wx[i][4], wx[i][5])
            }
        }

        // ---- C: store x(t+1) into other x buffer (consumed next iter, after sync) ----
        if (doX) {
            float* xb = sm + SM_XS + (tp & 1) * 1280;
            ((float2*)xb)[(2 * xfq) * 10 + xsl]     = make_float2(xv.x, xv.y);
            ((float2*)xb)[(2 * xfq + 1) * 10 + xsl] = make_float2(xv.z, xv.w);
        }

        // ---- D: wait for h(t) from all group CTAs ----
        if (t > 0) poll_flags(gflag, (unsigned)t, lane);

        // ---- E: stage h(t) tile 8KB from buffer cur (both LDGs before STS: MLP=2) ----
        {
            const float4* Hg4 = (const float4*)(&d_Hbuf[cur][g << 11]);
            float4* hs4w = (float4*)hs;
            int f0 = tid, f1 = tid + 256;
            float4 v0 = __ldcg(Hg4 + f0);
            float4 v1 = __ldcg(Hg4 + f1);
            hs4w[(f0 >> 2) * 5 + (f0 & 3)] = v0;
            hs4w[(f1 >> 2) * 5 + (f1 & 3)] = v1;
        }
        __syncthreads();

        {
            // ---- F: recurrent part: 8 kpair iters x 48 FFMA2 ----
            #pragma unroll
            for (int i = 0; i < 8; i++) {
                const int q = (i << 4) + ks;
                const ulonglong2* hp = Hp + q * 5;
                ulonglong2 h0 = hp[0], h1 = hp[1], h2 = hp[2], h3 = hp[3];
                const ulonglong2* wp = Rp + q * 49 + dgq * 3;
                ulonglong2 A = wp[0], Bv = wp[1], Cv = wp[2];
                FB6(0, h0.x, A.x, A.y, Bv.x, Bv.y, Cv.x, Cv.y)
                FB6(1, h0.y, A.x, A.y, Bv.x, Bv.y, Cv.x, Cv.y)
                FB6(2, h1.x, A.x, A.y, Bv.x, Bv.y, Cv.x, Cv.y)
                FB6(3, h1.y, A.x, A.y, Bv.x, Bv.y, Cv.x, Cv.y)
                FB6(4, h2.x, A.x, A.y, Bv.x, Bv.y, Cv.x, Cv.y)
                FB6(5, h2.y, A.x, A.y, Bv.x, Bv.y, Cv.x, Cv.y)
                FB6(6, h3.x, A.x, A.y, Bv.x, Bv.y, Cv.x, Cv.y)
                FB6(7, h3.y, A.x, A.y, Bv.x, Bv.y, Cv.x, Cv.y)
            }

            // ---- G: 4-round shedding butterfly over ks bits (packed u64) ----
            u64 r24[8][3];
            {
                const bool hi = down != 0;
                #pragma unroll
                for (int bi = 0; bi < 8; bi++)
                    #pragma unroll
                    for (int gt = 0; gt < 3; gt++) {
                        u64 send = hi ? acc[bi][gt] : acc[bi][3 + gt];
                        u64 recv = __shfl_xor_sync(0xffffffffu, send, 8);
                        u64 keep = hi ? acc[bi][3 + gt] : acc[bi][gt];
                        r24[bi][gt] = add2(keep, recv);
                    }
            }
            u64 r12[4][3];
            {
                const bool hb = (ks & 4) != 0;
                #pragma unroll
                for (int bi = 0; bi < 4; bi++)
                    #pragma unroll
                    for (int gt = 0; gt < 3; gt++) {
                        u64 send = hb ? r24[bi][gt] : r24[4 + bi][gt];
                        u64 recv = __shfl_xor_sync(0xffffffffu, send, 4);
                        u64 keep = hb ? r24[4 + bi][gt] : r24[bi][gt];
                        r12[bi][gt] = add2(keep, recv);
                    }
            }
            u64 r6[2][3];
            {
                const bool hb = (ks & 2) != 0;
                #pragma unroll
                for (int bi = 0; bi < 2; bi++)
                    #pragma unroll
                    for (int gt = 0; gt < 3; gt++) {
                        u64 send = hb ? r12[bi][gt] : r12[2 + bi][gt];
                        u64 recv = __shfl_xor_sync(0xffffffffu, send, 2);
                        u64 keep = hb ? r12[2 + bi][gt] : r12[bi][gt];
                        r6[bi][gt] = add2(keep, recv);
                    }
            }
            u64 r3[3];
            {
                const bool hb = (ks & 1) != 0;
                #pragma unroll
                for (int gt = 0; gt < 3; gt++) {
                    u64 send = hb ? r6[0][gt] : r6[1][gt];
                    u64 recv = __shfl_xor_sync(0xffffffffu, send, 1);
                    u64 keep = hb ? r6[1][gt] : r6[0][gt];
                    r3[gt] = add2(keep, recv);
                }
            }

            // ---- H: cell update; publish h(t+1) into buffer nxt ----
            if (t < myT) {
                float2 u0 = unpk(r3[0]), u1 = unpk(r3[1]), u2 = unpk(r3[2]);
                float p0 = u0.x + u0.y + b0c;
                float p1 = u1.x + u1.y + b1c;
                float p2 = u2.x + u2.y + b2c;
                if (t >= mylen) { p0 += t0c; p1 += t1c; p2 += t2c; }
                c = fmaf(ftanh(p0), fsig(p1), c);
                h = ftanh(c) * fsig(p2);
                __stcg(&d_Hbuf[nxt][(g << 11) + (jglob >> 1) * 16 + sown * 2 + (jglob & 1)], h);
                if (t == myT - 1) d_Hfinal[myb * HN + jglob] = h;
            }
        }
#undef FB6

        // ---- I: arrive: all CTA stores done -> release own flag ----
        __syncthreads();
        if (tid == 0) {
            asm volatile("st.release.gpu.global.u32 [%0], %1;"
                         :: "l"(myflag), "r"((unsigned)tp) : "memory");
        }
        cur = nxt;
    }

    // ---- wait for whole group, then fused projections ----
    poll_flags(gflag, (unsigned)gMaxT, lane);
    __syncthreads();

    const int ob = sperm[(g << 3) + di];
    float* hrow = sm + SM_PRJ;
    float* tmp  = hrow + 256;
    hrow[tid] = __ldcg(&d_Hfinal[ob * HN + tid]);
    __syncthreads();
    {
        const float4* wrow = (const float4*)(Wp + tid * HN);
        const float4* hv = (const float4*)hrow;
        float acc = __ldg(&bp[tid]);
        #pragma unroll 8
        for (int q = 0; q < HN / 4; q++) {
            float4 w = __ldg(&wrow[q]);
            float4 hh = hv[q];
            acc = fmaf(w.x, hh.x, acc); acc = fmaf(w.y, hh.y, acc);
            acc = fmaf(w.z, hh.z, acc); acc = fmaf(w.w, hh.w, acc);
        }
        tmp[tid] = acc;
    }
    __syncthreads();
    if (tid < 128) {
        const float4* wrow = (const float4*)(Wo + tid * HN);
        const float4* tv = (const float4*)tmp;
        float acc = __ldg(&bo[tid]);
        #pragma unroll 8
        for (int q = 0; q < HN / 4; q++) {
            float4 w = __ldg(&wrow[q]);
            float4 tt = tv[q];
            acc = fmaf(w.x, tt.x, acc); acc = fmaf(w.y, tt.y, acc);
            acc = fmaf(w.z, tt.z, acc); acc = fmaf(w.w, tt.w, acc);
        }
        out[ob * 128 + tid] = acc;
    }
}

extern "C" void kernel_launch(void* const* d_in, const int* in_sizes, int n_in,
                              void* d_out, int out_size) {
    const float* x    = (const float*)d_in[0];
    const int*   lens = (const int*)d_in[1];
    const float* W    = (const float*)d_in[2];
    const float* R    = (const float*)d_in[3];
    const float* b    = (const float*)d_in[4];
    const float* bt   = (const float*)d_in[5];
    const float* Wp   = (const float*)d_in[6];
    const float* bp   = (const float*)d_in[7];
    const float* Wo   = (const float*)d_in[8];
    const float* bo   = (const float*)d_in[9];
    float* out = (float*)d_out;

    cudaFuncSetAttribute(lstm_kernel, cudaFuncAttributeMaxDynamicSharedMemorySize, SMEM_BYTES);

    setup_kernel<<<1, NTH>>>(lens);
    lstm_kernel<<<NC, NTH, SMEM_BYTES>>>(x, W, R, b, bt, Wp, bp, Wo, bo, out);
}